// round 1
// baseline (speedup 1.0000x reference)
#include <cuda_runtime.h>

// Problem constants
#define A_   96
#define DET0_ 256
#define T_   256
#define NZ_  32
#define NY_  256
#define NX_  256
#define DTH  0.0327249234748936795f   // pi/96 (fp32)
#define LAMB_ 0.01f

// Scratch (device globals; no allocation)
__device__ float g_vol_t[NY_ * NX_ * NZ_];      // [y][x][z], z fastest (8 MB)
__device__ float g_res_t[A_ * DET0_ * NZ_];     // [a][u][z], z fastest (3 MB)

__device__ __forceinline__ void fma4(float4& a, float w, const float4 v) {
    a.x = fmaf(w, v.x, a.x);
    a.y = fmaf(w, v.y, a.y);
    a.z = fmaf(w, v.z, a.z);
    a.w = fmaf(w, v.w, a.w);
}

// ---------------------------------------------------------------------------
// Kernel 1: transpose x (z,y,x) -> vol_t (y,x,z)
// grid (NX/32, NY), block (32,32). Coalesced read and write via smem tile.
// ---------------------------------------------------------------------------
__global__ __launch_bounds__(1024) void transpose_kernel(const float* __restrict__ x) {
    __shared__ float tile[32][33];
    const int xb = blockIdx.x * 32;
    const int y  = blockIdx.y;
    // read: lanes over x (coalesced), rows over z
    tile[threadIdx.y][threadIdx.x] =
        x[threadIdx.y * (NY_ * NX_) + y * NX_ + xb + threadIdx.x];
    __syncthreads();
    // write: lanes over z (contiguous 128B per (y,x) cell)
    g_vol_t[(y * NX_ + xb + threadIdx.y) * NZ_ + threadIdx.x] =
        tile[threadIdx.x][threadIdx.y];
}

// ---------------------------------------------------------------------------
// Kernel 2: forward project + residual.
// Block = (angle, 32-u tile), 128 threads. Lane: zq = tid&3 (8 z's as 2 float4),
// u_local = tid>>2 (32 u's). Sequential t loop, register accumulators.
// Writes res_t[a][u][z] = S[a][z][u] - p(reordered).
// ---------------------------------------------------------------------------
__global__ __launch_bounds__(128) void fwd_kernel(const float* __restrict__ p) {
    const float4* __restrict__ vol4 = reinterpret_cast<const float4*>(g_vol_t);

    const int tid = threadIdx.x;
    const int zq  = tid & 3;        // float4 slot: z = 4*zq..4*zq+3 and 16+4*zq..
    const int ul  = tid >> 2;       // 0..31
    const int a   = blockIdx.y;
    const int u   = blockIdx.x * 32 + ul;

    float s, c;
    sincosf((float)a * DTH, &s, &c);

    const float uc = (float)u - 127.5f;
    const float bx = fmaf(uc, -s, 127.5f);   // ix at t-center
    const float by = fmaf(uc,  c, 127.5f);   // iy at t-center

    float4 acc0 = make_float4(0.f, 0.f, 0.f, 0.f);
    float4 acc1 = make_float4(0.f, 0.f, 0.f, 0.f);

    #pragma unroll 4
    for (int t = 0; t < T_; ++t) {
        const float tf = (float)t - 127.5f;
        const float ix = fmaf(tf, c, bx);
        const float iy = fmaf(tf, s, by);

        const int x0 = __float2int_rd(ix);
        const int y0 = __float2int_rd(iy);
        // keep only if x0 in [-1,255] and y0 in [-1,255] (else all 4 taps invalid)
        if ((unsigned)(x0 + 1) > 256u || (unsigned)(y0 + 1) > 256u) continue;

        const float fx = ix - (float)x0;
        const float fy = iy - (float)y0;

        const float wx0 = (x0 >= 0)   ? (1.0f - fx) : 0.0f;
        const float wx1 = (x0 <= 254) ? fx          : 0.0f;
        const float wy0 = (y0 >= 0)   ? (1.0f - fy) : 0.0f;
        const float wy1 = (y0 <= 254) ? fy          : 0.0f;

        const int xc0 = max(x0, 0);
        const int yc0 = max(y0, 0);
        const int xc1 = min(x0 + 1, 255);
        const int yc1 = min(y0 + 1, 255);

        const int r0 = yc0 << 8;
        const int r1 = yc1 << 8;
        const int i00 = (r0 + xc0) * 8 + zq;
        const int i01 = (r0 + xc1) * 8 + zq;
        const int i10 = (r1 + xc0) * 8 + zq;
        const int i11 = (r1 + xc1) * 8 + zq;

        const float w00 = wy0 * wx0;
        const float w01 = wy0 * wx1;
        const float w10 = wy1 * wx0;
        const float w11 = wy1 * wx1;

        fma4(acc0, w00, vol4[i00]); fma4(acc1, w00, vol4[i00 + 4]);
        fma4(acc0, w01, vol4[i01]); fma4(acc1, w01, vol4[i01 + 4]);
        fma4(acc0, w10, vol4[i10]); fma4(acc1, w10, vol4[i10 + 4]);
        fma4(acc0, w11, vol4[i11]); fma4(acc1, w11, vol4[i11 + 4]);
    }

    // Residual: res[a,z,u] = S[a,z,u] - p[(a*4 + m>>3), m&7, u], m = ((z&7)<<2)|(z>>3)
    float accv[8] = {acc0.x, acc0.y, acc0.z, acc0.w, acc1.x, acc1.y, acc1.z, acc1.w};
    float r[8];
    #pragma unroll
    for (int e = 0; e < 8; ++e) {
        const int z = (e < 4) ? (4 * zq + e) : (16 + 4 * zq + (e - 4));
        const int m = ((z & 7) << 2) | (z >> 3);
        const float pv = p[(a * 4 + (m >> 3)) * (8 * 256) + (m & 7) * 256 + u];
        r[e] = accv[e] - pv;
    }

    float4* res4 = reinterpret_cast<float4*>(g_res_t);
    const int ob = (a * 256 + u) * 8;
    res4[ob + zq]     = make_float4(r[0], r[1], r[2], r[3]);
    res4[ob + 4 + zq] = make_float4(r[4], r[5], r[6], r[7]);
}

// ---------------------------------------------------------------------------
// Kernel 3: back project. Block = 16x4 pixel tile, 256 threads.
// Lane: zq = tid&3 (8 z's), slot = tid>>2 -> pixel (sx 0..15, sy 0..3).
// Loops all 96 angles; res slice per angle (32 KB) is L1-resident.
// ---------------------------------------------------------------------------
__global__ __launch_bounds__(256) void bwd_kernel(float* __restrict__ out) {
    __shared__ float2 ang[A_];
    const int tid = threadIdx.x;
    if (tid < A_) {
        float s, c;
        sincosf((float)tid * DTH, &s, &c);
        ang[tid] = make_float2(s, c);
    }
    __syncthreads();

    const int zq   = tid & 3;
    const int slot = tid >> 2;
    const int sx   = slot & 15;
    const int sy   = slot >> 4;
    const int x = blockIdx.x * 16 + sx;
    const int y = blockIdx.y * 4 + sy;

    const float Xc = (float)x - 127.5f;
    const float Yc = (float)y - 127.5f;

    const float4* __restrict__ res4 = reinterpret_cast<const float4*>(g_res_t);

    float4 acc0 = make_float4(0.f, 0.f, 0.f, 0.f);
    float4 acc1 = make_float4(0.f, 0.f, 0.f, 0.f);

    #pragma unroll 2
    for (int a = 0; a < A_; ++a) {
        const float s = ang[a].x;
        const float c = ang[a].y;
        const float ub = fmaf(Yc, c, fmaf(Xc, -s, 127.5f));
        const int u0 = __float2int_rd(ub);
        if ((unsigned)(u0 + 1) > 256u) continue;   // both taps invalid

        const float fu = ub - (float)u0;
        const float w0 = (u0 >= 0)   ? (1.0f - fu) : 0.0f;
        const float w1 = (u0 <= 254) ? fu          : 0.0f;
        const int uc0 = max(u0, 0);
        const int uc1 = min(u0 + 1, 255);

        const int b0 = (a * 256 + uc0) * 8 + zq;
        const int b1 = (a * 256 + uc1) * 8 + zq;

        fma4(acc0, w0, res4[b0]); fma4(acc1, w0, res4[b0 + 4]);
        fma4(acc0, w1, res4[b1]); fma4(acc1, w1, res4[b1 + 4]);
    }

    const int base = y * NX_ + x;
    const float L = -LAMB_;
    out[(4 * zq + 0) * (NY_ * NX_) + base] = L * acc0.x;
    out[(4 * zq + 1) * (NY_ * NX_) + base] = L * acc0.y;
    out[(4 * zq + 2) * (NY_ * NX_) + base] = L * acc0.z;
    out[(4 * zq + 3) * (NY_ * NX_) + base] = L * acc0.w;
    out[(16 + 4 * zq + 0) * (NY_ * NX_) + base] = L * acc1.x;
    out[(16 + 4 * zq + 1) * (NY_ * NX_) + base] = L * acc1.y;
    out[(16 + 4 * zq + 2) * (NY_ * NX_) + base] = L * acc1.z;
    out[(16 + 4 * zq + 3) * (NY_ * NX_) + base] = L * acc1.w;
}

// ---------------------------------------------------------------------------
extern "C" void kernel_launch(void* const* d_in, const int* in_sizes, int n_in,
                              void* d_out, int out_size) {
    const float* x = (const float*)d_in[0];
    const float* p = (const float*)d_in[1];
    // defensive: identify by size (x: 32*256*256 = 2097152, p: 384*8*256 = 786432)
    if (n_in >= 2 && in_sizes[0] == 786432) {
        const float* tmp = x; x = p; p = tmp;
    }
    float* out = (float*)d_out;

    transpose_kernel<<<dim3(NX_ / 32, NY_), dim3(32, 32)>>>(x);
    fwd_kernel<<<dim3(DET0_ / 32, A_), 128>>>(p);
    bwd_kernel<<<dim3(NX_ / 16, NY_ / 4), 256>>>(out);
}

// round 2
// speedup vs baseline: 1.2255x; 1.2255x over previous
#include <cuda_runtime.h>

// Problem constants
#define A_    96
#define DET0_ 256
#define T_    256
#define NZ_   32
#define NY_   256
#define NX_   256
#define DTH   0.0327249234748936795f   // pi/96 (fp32)
#define LAMB_ 0.01f

// Scratch (device globals; no allocation)
__device__ float g_vol_t[NY_ * NX_ * NZ_];      // [y][x][z], z fastest (8 MB)
__device__ float g_res_t[A_ * DET0_ * NZ_];     // [a][u][z], z fastest (3 MB)

__device__ __forceinline__ void fma4(float4& a, float w, const float4 v) {
    a.x = fmaf(w, v.x, a.x);
    a.y = fmaf(w, v.y, a.y);
    a.z = fmaf(w, v.z, a.z);
    a.w = fmaf(w, v.w, a.w);
}

// ---------------------------------------------------------------------------
// Kernel 1: transpose x (z,y,x) -> vol_t (y,x,z).
// Read coalesced scalar; write vectorized STG.128 (full cell lines).
// ---------------------------------------------------------------------------
__global__ __launch_bounds__(1024) void transpose_kernel(const float* __restrict__ x) {
    __shared__ float tile[32][33];   // [z][x]
    const int xb = blockIdx.x * 32;
    const int y  = blockIdx.y;
    tile[threadIdx.y][threadIdx.x] =
        x[threadIdx.y * (NY_ * NX_) + y * NX_ + xb + threadIdx.x];
    __syncthreads();
    const int tid = threadIdx.y * 32 + threadIdx.x;
    if (tid < 256) {
        const int tz = tid & 7;    // float4 slot along z
        const int xl = tid >> 3;   // 0..31
        // smem banks: (4*tz+k)*33 + xl -> 4*tz + k + xl mod 32, distinct per warp
        float4 v = make_float4(tile[4 * tz + 0][xl], tile[4 * tz + 1][xl],
                               tile[4 * tz + 2][xl], tile[4 * tz + 3][xl]);
        reinterpret_cast<float4*>(g_vol_t)[(y * NX_ + xb + xl) * 8 + tz] = v;
    }
}

// ---------------------------------------------------------------------------
// Kernel 2: forward project + residual.
// Block = (angle, 32-u tile), 256 threads. Lane: zo = tid&7 (one float4 =
// 4 z's; 8 lanes per u cover the full 128B cell line -> full-line LDG.128),
// ul = tid>>3 (32 u's). Sequential t loop, register accumulators.
// Writes res_t[a][u][z] = S[a][z][u] - p(reordered).
// ---------------------------------------------------------------------------
__global__ __launch_bounds__(256) void fwd_kernel(const float* __restrict__ p) {
    const float4* __restrict__ vol4 = reinterpret_cast<const float4*>(g_vol_t);

    const int tid = threadIdx.x;
    const int zo  = tid & 7;        // float4 slot: z = 4*zo .. 4*zo+3
    const int ul  = tid >> 3;       // 0..31
    const int a   = blockIdx.y;
    const int u   = blockIdx.x * 32 + ul;

    float s, c;
    sincosf((float)a * DTH, &s, &c);

    const float uc = (float)u - 127.5f;
    const float bx = fmaf(uc, -s, 127.5f);   // ix at t-center
    const float by = fmaf(uc,  c, 127.5f);   // iy at t-center

    float4 acc_a = make_float4(0.f, 0.f, 0.f, 0.f);
    float4 acc_b = make_float4(0.f, 0.f, 0.f, 0.f);

    #pragma unroll 4
    for (int t = 0; t < T_; ++t) {
        const float tf = (float)t - 127.5f;
        const float ix = fmaf(tf, c, bx);
        const float iy = fmaf(tf, s, by);

        const int x0 = __float2int_rd(ix);
        const int y0 = __float2int_rd(iy);
        if ((unsigned)(x0 + 1) > 256u || (unsigned)(y0 + 1) > 256u) continue;

        const float fx = ix - (float)x0;
        const float fy = iy - (float)y0;

        const float wx0 = (x0 >= 0)   ? (1.0f - fx) : 0.0f;
        const float wx1 = (x0 <= 254) ? fx          : 0.0f;
        const float wy0 = (y0 >= 0)   ? (1.0f - fy) : 0.0f;
        const float wy1 = (y0 <= 254) ? fy          : 0.0f;

        const int xc0 = max(x0, 0);
        const int yc0 = max(y0, 0);
        const int xc1 = min(x0 + 1, 255);
        const int yc1 = min(y0 + 1, 255);

        const int r0 = yc0 << 8;
        const int r1 = yc1 << 8;
        const int i00 = (r0 + xc0) * 8 + zo;
        const int i01 = (r0 + xc1) * 8 + zo;
        const int i10 = (r1 + xc0) * 8 + zo;
        const int i11 = (r1 + xc1) * 8 + zo;

        fma4(acc_a, wy0 * wx0, vol4[i00]);
        fma4(acc_b, wy0 * wx1, vol4[i01]);
        fma4(acc_a, wy1 * wx0, vol4[i10]);
        fma4(acc_b, wy1 * wx1, vol4[i11]);
    }

    const float accv[4] = {acc_a.x + acc_b.x, acc_a.y + acc_b.y,
                           acc_a.z + acc_b.z, acc_a.w + acc_b.w};
    float r[4];
    #pragma unroll
    for (int e = 0; e < 4; ++e) {
        const int z = 4 * zo + e;
        const int m = ((z & 7) << 2) | (z >> 3);
        const float pv = p[(a * 4 + (m >> 3)) * (8 * 256) + (m & 7) * 256 + u];
        r[e] = accv[e] - pv;
    }

    float4* res4 = reinterpret_cast<float4*>(g_res_t);
    res4[(a * 256 + u) * 8 + zo] = make_float4(r[0], r[1], r[2], r[3]);
}

// ---------------------------------------------------------------------------
// Kernel 3: back project. Block = 8x4 pixel tile, 256 threads.
// Lane: zo = tid&7 (one float4 = 4 z's; 8 lanes per pixel cover the full
// 128B res line), slot = tid>>3 -> pixel.
// ---------------------------------------------------------------------------
__global__ __launch_bounds__(256) void bwd_kernel(float* __restrict__ out) {
    __shared__ float2 ang[A_];
    const int tid = threadIdx.x;
    if (tid < A_) {
        float s, c;
        sincosf((float)tid * DTH, &s, &c);
        ang[tid] = make_float2(s, c);
    }
    __syncthreads();

    const int zo   = tid & 7;
    const int slot = tid >> 3;      // 0..31
    const int sx   = slot & 7;
    const int sy   = slot >> 3;
    const int x = blockIdx.x * 8 + sx;
    const int y = blockIdx.y * 4 + sy;

    const float Xc = (float)x - 127.5f;
    const float Yc = (float)y - 127.5f;

    const float4* __restrict__ res4 = reinterpret_cast<const float4*>(g_res_t);

    float4 acc_a = make_float4(0.f, 0.f, 0.f, 0.f);
    float4 acc_b = make_float4(0.f, 0.f, 0.f, 0.f);

    #pragma unroll 4
    for (int a = 0; a < A_; ++a) {
        const float s = ang[a].x;
        const float c = ang[a].y;
        const float ub = fmaf(Yc, c, fmaf(Xc, -s, 127.5f));
        const int u0 = __float2int_rd(ub);
        if ((unsigned)(u0 + 1) > 256u) continue;   // both taps invalid

        const float fu = ub - (float)u0;
        const float w0 = (u0 >= 0)   ? (1.0f - fu) : 0.0f;
        const float w1 = (u0 <= 254) ? fu          : 0.0f;
        const int uc0 = max(u0, 0);
        const int uc1 = min(u0 + 1, 255);

        fma4(acc_a, w0, res4[(a * 256 + uc0) * 8 + zo]);
        fma4(acc_b, w1, res4[(a * 256 + uc1) * 8 + zo]);
    }

    const float L = -LAMB_;
    const int base = y * NX_ + x;
    out[(4 * zo + 0) * (NY_ * NX_) + base] = L * (acc_a.x + acc_b.x);
    out[(4 * zo + 1) * (NY_ * NX_) + base] = L * (acc_a.y + acc_b.y);
    out[(4 * zo + 2) * (NY_ * NX_) + base] = L * (acc_a.z + acc_b.z);
    out[(4 * zo + 3) * (NY_ * NX_) + base] = L * (acc_a.w + acc_b.w);
}

// ---------------------------------------------------------------------------
extern "C" void kernel_launch(void* const* d_in, const int* in_sizes, int n_in,
                              void* d_out, int out_size) {
    const float* x = (const float*)d_in[0];
    const float* p = (const float*)d_in[1];
    if (n_in >= 2 && in_sizes[0] == 786432) {   // defensive swap by size
        const float* tmp = x; x = p; p = tmp;
    }
    float* out = (float*)d_out;

    transpose_kernel<<<dim3(NX_ / 32, NY_), dim3(32, 32)>>>(x);
    fwd_kernel<<<dim3(DET0_ / 32, A_), 256>>>(p);
    bwd_kernel<<<dim3(NX_ / 8, NY_ / 4), 256>>>(out);
}